// round 3
// baseline (speedup 1.0000x reference)
#include <cuda_runtime.h>
#include <cuda_bf16.h>

// GCN 2-layer forward:
//   deg = in-degree(dst) + 1 (self loop); dinv = rsqrt(deg)
//   t1 = dinv[i] * (x @ W1)
//   r  = relu(dinv[i] * (t1[i] + sum_{s in in(i)} t1[s]) + b1)
//   t2 = dinv[i] * (r @ W2)
//   out= dinv[i] * (t2[i] + sum_{s in in(i)} t2[s]) + b2
// Aggregation is pull-based via a per-launch CSR (bucket-by-dst) build.

#define MAXN 50000
#define MAXE 800000
#define C1 128
#define C2 64

__device__ int   g_is64;
__device__ int   g_cnt[MAXN];
__device__ int   g_off[MAXN + 1];
__device__ int   g_cur[MAXN];
__device__ int   g_srcl[MAXE];
__device__ int   g_part[64];
__device__ float g_dinv[MAXN];
__device__ float g_t1[MAXN * C1];
__device__ float g_r[MAXN * C1];
__device__ float g_t2[MAXN * C2];

// ---------------------------------------------------------------------------
// Detect whether edge_index is int64 or int32 (jax x64 canonicalization).
// If int32, reading as int64 gives values >= 2^32 (node ids < 50000) almost
// surely within the first 64 words.
__global__ void k_detect(const void* ei, int n_nodes, long long safe_words) {
    if (threadIdx.x == 0 && blockIdx.x == 0) {
        const unsigned long long* p = (const unsigned long long*)ei;
        long long cnt = safe_words < 64 ? safe_words : 64;
        int ok64 = 1;
        for (long long i = 0; i < cnt; i++) {
            if (p[i] >= (unsigned long long)n_nodes) { ok64 = 0; break; }
        }
        g_is64 = ok64;
    }
}

__device__ __forceinline__ int load_edge(const void* ei, long long idx, int is64) {
    if (is64) return (int)((const long long*)ei)[idx];
    return ((const int*)ei)[idx];
}

__global__ void k_zero_cnt(int n) {
    int i = blockIdx.x * blockDim.x + threadIdx.x;
    if (i < n) g_cnt[i] = 0;
}

__global__ void k_count(const void* ei, long long E) {
    long long e = (long long)blockIdx.x * blockDim.x + threadIdx.x;
    if (e < E) {
        int is64 = g_is64;
        int d = load_edge(ei, E + e, is64);
        atomicAdd(&g_cnt[d], 1);
    }
}

// ---------------------------------------------------------------------------
// Two-level exclusive scan of g_cnt -> g_off
__global__ void k_scan1(int n) {
    __shared__ int s[1024];
    int tid = threadIdx.x;
    int gid = blockIdx.x * 1024 + tid;
    int v = (gid < n) ? g_cnt[gid] : 0;
    s[tid] = v;
    __syncthreads();
#pragma unroll
    for (int o = 1; o < 1024; o <<= 1) {
        int t = (tid >= o) ? s[tid - o] : 0;
        __syncthreads();
        s[tid] += t;
        __syncthreads();
    }
    if (gid < n) g_off[gid] = s[tid] - v;  // exclusive
    if (tid == 1023) g_part[blockIdx.x] = s[tid];
}

__global__ void k_scan2(int nb) {
    __shared__ int s[64];
    int tid = threadIdx.x;
    int v = (tid < nb) ? g_part[tid] : 0;
    s[tid] = v;
    __syncthreads();
#pragma unroll
    for (int o = 1; o < 64; o <<= 1) {
        int t = (tid >= o) ? s[tid - o] : 0;
        __syncthreads();
        s[tid] += t;
        __syncthreads();
    }
    if (tid < nb) g_part[tid] = s[tid] - v;  // exclusive block offsets
}

__global__ void k_scan3(int n, long long E) {
    int i = blockIdx.x * blockDim.x + threadIdx.x;
    if (i < n) {
        int off = g_off[i] + g_part[i >> 10];
        g_off[i] = off;
        g_cur[i] = off;
        g_dinv[i] = rsqrtf((float)(g_cnt[i] + 1));
    }
    if (i == 0) g_off[n] = (int)E;
}

__global__ void k_bucket(const void* ei, long long E) {
    long long e = (long long)blockIdx.x * blockDim.x + threadIdx.x;
    if (e < E) {
        int is64 = g_is64;
        int s = load_edge(ei, e, is64);
        int d = load_edge(ei, E + e, is64);
        int pos = atomicAdd(&g_cur[d], 1);
        g_srcl[pos] = s;
    }
}

// ---------------------------------------------------------------------------
// Tiled fp32 GEMM with row-scale epilogue: C[m][c] = dinv[m] * sum_k A[m][k]*W[k][c]
// K = 128 fixed; NC = 128 or 64. BM=64, BK=16, 256 threads.
template <int NC>
__global__ __launch_bounds__(256) void k_gemm_scale(
    const float* __restrict__ A, const float* __restrict__ W,
    float* __restrict__ C, int M)
{
    constexpr int K  = 128;
    constexpr int BM = 64;
    constexpr int BK = 16;
    constexpr int BN = NC;
    constexpr int TM = 4;
    constexpr int TN = BN / 16;

    __shared__ float As[BK][BM];
    __shared__ float Bs[BK][BN];

    int tid = threadIdx.x;
    int tx = tid & 15;
    int ty = tid >> 4;
    int rowBase = blockIdx.x * BM;

    int la_row = tid >> 2;        // 0..63
    int la_k   = (tid & 3) * 4;   // 0,4,8,12

    float acc[TM][TN];
#pragma unroll
    for (int i = 0; i < TM; i++)
#pragma unroll
        for (int j = 0; j < TN; j++) acc[i][j] = 0.0f;

    for (int kc = 0; kc < K; kc += BK) {
        // Load A tile (transposed into As[k][m])
        int gr = rowBase + la_row;
        float4 av = make_float4(0.f, 0.f, 0.f, 0.f);
        if (gr < M) av = *(const float4*)&A[(long long)gr * K + kc + la_k];
        As[la_k + 0][la_row] = av.x;
        As[la_k + 1][la_row] = av.y;
        As[la_k + 2][la_row] = av.z;
        As[la_k + 3][la_row] = av.w;

        // Load B tile
#pragma unroll
        for (int idx = tid; idx < BK * BN / 4; idx += 256) {
            int kk = idx / (BN / 4);
            int cc = (idx % (BN / 4)) * 4;
            *(float4*)&Bs[kk][cc] = *(const float4*)&W[(kc + kk) * NC + cc];
        }
        __syncthreads();

#pragma unroll
        for (int k = 0; k < BK; k++) {
            float a[TM], b[TN];
#pragma unroll
            for (int i = 0; i < TM; i++) a[i] = As[k][ty * TM + i];
#pragma unroll
            for (int j = 0; j < TN; j++) b[j] = Bs[k][tx * TN + j];
#pragma unroll
            for (int i = 0; i < TM; i++)
#pragma unroll
                for (int j = 0; j < TN; j++) acc[i][j] += a[i] * b[j];
        }
        __syncthreads();
    }

#pragma unroll
    for (int i = 0; i < TM; i++) {
        int r = rowBase + ty * TM + i;
        if (r < M) {
            float di = g_dinv[r];
#pragma unroll
            for (int j = 0; j < TN; j += 4) {
                float4 v;
                v.x = di * acc[i][j + 0];
                v.y = di * acc[i][j + 1];
                v.z = di * acc[i][j + 2];
                v.w = di * acc[i][j + 3];
                *(float4*)&C[(long long)r * NC + tx * TN + j] = v;
            }
        }
    }
}

// ---------------------------------------------------------------------------
// Pull aggregation layer 1: warp per node, 128 channels as float4 per lane.
// r[i] = relu(dinv[i] * (t1[i] + sum t1[src]) + b1)
__global__ __launch_bounds__(256) void k_pull1(const float* __restrict__ b1, int n) {
    int w = (blockIdx.x * blockDim.x + threadIdx.x) >> 5;
    int lane = threadIdx.x & 31;
    if (w >= n) return;
    const float4* t1v = (const float4*)g_t1;
    float4 acc = t1v[(long long)w * 32 + lane];
    int e0 = g_off[w], e1 = g_off[w + 1];
    for (int e = e0; e < e1; e++) {
        int s = g_srcl[e];
        float4 v = t1v[(long long)s * 32 + lane];
        acc.x += v.x; acc.y += v.y; acc.z += v.z; acc.w += v.w;
    }
    float di = g_dinv[w];
    float4 bb = ((const float4*)b1)[lane];
    float4 r;
    r.x = fmaxf(fmaf(di, acc.x, bb.x), 0.0f);
    r.y = fmaxf(fmaf(di, acc.y, bb.y), 0.0f);
    r.z = fmaxf(fmaf(di, acc.z, bb.z), 0.0f);
    r.w = fmaxf(fmaf(di, acc.w, bb.w), 0.0f);
    ((float4*)g_r)[(long long)w * 32 + lane] = r;
}

// Pull aggregation layer 2: warp per node, 64 channels as float2 per lane.
// out[i] = dinv[i] * (t2[i] + sum t2[src]) + b2
__global__ __launch_bounds__(256) void k_pull2(const float* __restrict__ b2,
                                               float* __restrict__ out, int n) {
    int w = (blockIdx.x * blockDim.x + threadIdx.x) >> 5;
    int lane = threadIdx.x & 31;
    if (w >= n) return;
    const float2* t2v = (const float2*)g_t2;
    float2 acc = t2v[(long long)w * 32 + lane];
    int e0 = g_off[w], e1 = g_off[w + 1];
    for (int e = e0; e < e1; e++) {
        int s = g_srcl[e];
        float2 v = t2v[(long long)s * 32 + lane];
        acc.x += v.x; acc.y += v.y;
    }
    float di = g_dinv[w];
    float2 bb = ((const float2*)b2)[lane];
    float2 r;
    r.x = fmaf(di, acc.x, bb.x);
    r.y = fmaf(di, acc.y, bb.y);
    ((float2*)out)[(long long)w * 32 + lane] = r;
}

// ---------------------------------------------------------------------------
extern "C" void kernel_launch(void* const* d_in, const int* in_sizes, int n_in,
                              void* d_out, int out_size) {
    const float* x  = (const float*)d_in[0];
    const void*  ei = d_in[1];
    const float* W1 = (const float*)d_in[2];
    const float* b1 = (const float*)d_in[3];
    const float* W2 = (const float*)d_in[4];
    const float* b2 = (const float*)d_in[5];
    float* out = (float*)d_out;

    int N = in_sizes[0] / C1;            // 50000
    long long E = in_sizes[1] / 2;       // 800000 (element count is dtype-agnostic)

    // Real device addresses of the scratch symbols (host-side symbol names are
    // shadows; passing them directly as kernel args is UB — R1 bug).
    float *p_t1 = nullptr, *p_r = nullptr, *p_t2 = nullptr;
    cudaGetSymbolAddress((void**)&p_t1, g_t1);
    cudaGetSymbolAddress((void**)&p_r,  g_r);
    cudaGetSymbolAddress((void**)&p_t2, g_t2);

    // safe int64-word count: if int32 actual, buffer holds E int64 words
    k_detect<<<1, 32>>>(ei, N, E);

    int gN = (N + 255) / 256;
    long long gE = (E + 255) / 256;

    k_zero_cnt<<<gN, 256>>>(N);
    k_count<<<(unsigned)gE, 256>>>(ei, E);

    int nb = (N + 1023) / 1024;
    k_scan1<<<nb, 1024>>>(N);
    k_scan2<<<1, 64>>>(nb);
    k_scan3<<<gN, 256>>>(N, E);
    k_bucket<<<(unsigned)gE, 256>>>(ei, E);

    int gg = (N + 63) / 64;
    k_gemm_scale<C1><<<gg, 256>>>(x, W1, p_t1, N);

    long long warpThreads = (long long)N * 32;
    int gw = (int)((warpThreads + 255) / 256);
    k_pull1<<<gw, 256>>>(b1, N);

    k_gemm_scale<C2><<<gg, 256>>>(p_r, W2, p_t2, N);

    k_pull2<<<gw, 256>>>(b2, out, N);
}

// round 4
// speedup vs baseline: 1.5824x; 1.5824x over previous
#include <cuda_runtime.h>
#include <cuda_bf16.h>

// GCN 2-layer forward, pull-based aggregation via per-launch CSR build.
//   t1 = dinv[i] * (x @ W1)                      [tf32 tensor-core GEMM]
//   r  = relu(dinv[i] * (t1[i] + sum t1[src]) + b1)
//   t2 = dinv[i] * (r @ W2)                      [tf32 tensor-core GEMM]
//   out= dinv[i] * (t2[i] + sum t2[src]) + b2

#define MAXN 50000
#define MAXE 800000
#define C1 128
#define C2 64

__device__ int   g_is64;
__device__ int   g_cnt[MAXN];
__device__ int   g_off[MAXN + 1];
__device__ int   g_cur[MAXN];
__device__ int   g_srcl[MAXE];
__device__ int   g_part[64];
__device__ float g_dinv[MAXN];
__device__ float g_t1[MAXN * C1];
__device__ float g_r[MAXN * C1];
__device__ float g_t2[MAXN * C2];

// ---------------------------------------------------------------------------
__global__ void k_detect(const void* ei, int n_nodes, long long safe_words) {
    if (threadIdx.x == 0 && blockIdx.x == 0) {
        const unsigned long long* p = (const unsigned long long*)ei;
        long long cnt = safe_words < 64 ? safe_words : 64;
        int ok64 = 1;
        for (long long i = 0; i < cnt; i++) {
            if (p[i] >= (unsigned long long)n_nodes) { ok64 = 0; break; }
        }
        g_is64 = ok64;
    }
}

__device__ __forceinline__ int load_edge(const void* ei, long long idx, int is64) {
    if (is64) return (int)((const long long*)ei)[idx];
    return ((const int*)ei)[idx];
}

__global__ void k_zero_cnt(int n) {
    int i = blockIdx.x * blockDim.x + threadIdx.x;
    if (i < n) g_cnt[i] = 0;
}

__global__ void k_count(const void* ei, long long E) {
    long long e = (long long)blockIdx.x * blockDim.x + threadIdx.x;
    if (e < E) {
        int d = load_edge(ei, E + e, g_is64);
        atomicAdd(&g_cnt[d], 1);
    }
}

__global__ void k_scan1(int n) {
    __shared__ int s[1024];
    int tid = threadIdx.x;
    int gid = blockIdx.x * 1024 + tid;
    int v = (gid < n) ? g_cnt[gid] : 0;
    s[tid] = v;
    __syncthreads();
#pragma unroll
    for (int o = 1; o < 1024; o <<= 1) {
        int t = (tid >= o) ? s[tid - o] : 0;
        __syncthreads();
        s[tid] += t;
        __syncthreads();
    }
    if (gid < n) g_off[gid] = s[tid] - v;
    if (tid == 1023) g_part[blockIdx.x] = s[tid];
}

__global__ void k_scan2(int nb) {
    __shared__ int s[64];
    int tid = threadIdx.x;
    int v = (tid < nb) ? g_part[tid] : 0;
    s[tid] = v;
    __syncthreads();
#pragma unroll
    for (int o = 1; o < 64; o <<= 1) {
        int t = (tid >= o) ? s[tid - o] : 0;
        __syncthreads();
        s[tid] += t;
        __syncthreads();
    }
    if (tid < nb) g_part[tid] = s[tid] - v;
}

__global__ void k_scan3(int n, long long E) {
    int i = blockIdx.x * blockDim.x + threadIdx.x;
    if (i < n) {
        int off = g_off[i] + g_part[i >> 10];
        g_off[i] = off;
        g_cur[i] = off;
        g_dinv[i] = rsqrtf((float)(g_cnt[i] + 1));
    }
    if (i == 0) g_off[n] = (int)E;
}

__global__ void k_bucket(const void* ei, long long E) {
    long long e = (long long)blockIdx.x * blockDim.x + threadIdx.x;
    if (e < E) {
        int is64 = g_is64;
        int s = load_edge(ei, e, is64);
        int d = load_edge(ei, E + e, is64);
        int pos = atomicAdd(&g_cur[d], 1);
        g_srcl[pos] = s;
    }
}

// ---------------------------------------------------------------------------
// tf32 tensor-core GEMM: C[m][c] = dinv[m] * sum_k A[m][k] * W[k][c]
// K=128 fixed. BM=128, BK=32, 256 threads (8 warps).
// Warp tile: 32 rows x (NC==128 ? 64 : 32) cols via m16n8k8 tf32 mma.
__device__ __forceinline__ unsigned f2tf32(float f) {
    unsigned u;
    asm("cvt.rna.tf32.f32 %0, %1;" : "=r"(u) : "f"(f));
    return u;
}

template <int NC>
__global__ __launch_bounds__(256) void k_gemm_tf32(
    const float* __restrict__ A, const float* __restrict__ W,
    float* __restrict__ C, int M)
{
    constexpr int K   = 128;
    constexpr int BM  = 128;
    constexpr int BK  = 32;
    constexpr int PA  = BK + 4;   // 36 — conflict-free A frag loads
    constexpr int PB  = NC + 4;   // 132 / 68
    constexpr int NF  = NC / 16;  // n8 frags per warp: 8 (NC=128) / 4 (NC=64)

    __shared__ unsigned As[BM * PA];
    __shared__ unsigned Bs[BK * PB];

    int tid  = threadIdx.x;
    int wid  = tid >> 5;
    int lane = tid & 31;
    int wm   = wid >> 1;          // 0..3  -> row block of 32
    int wn   = wid & 1;           // 0..1  -> col block of NF*8
    int g    = lane >> 2;         // 0..7
    int t    = lane & 3;          // 0..3
    int rowBase = blockIdx.x * BM;

    float acc[2][NF][4];
#pragma unroll
    for (int mf = 0; mf < 2; mf++)
#pragma unroll
        for (int nf = 0; nf < NF; nf++)
#pragma unroll
            for (int i = 0; i < 4; i++) acc[mf][nf][i] = 0.0f;

    for (int kc = 0; kc < K; kc += BK) {
        // --- load A tile [BM x BK] ---
#pragma unroll
        for (int it = 0; it < (BM * BK / 4) / 256; it++) {
            int idx = tid + it * 256;              // 0..1023
            int row = idx >> 3;
            int c4  = (idx & 7) * 4;
            int gr  = rowBase + row;
            float4 av = make_float4(0.f, 0.f, 0.f, 0.f);
            if (gr < M) av = *(const float4*)&A[(long long)gr * K + kc + c4];
            unsigned* dst = &As[row * PA + c4];
            dst[0] = f2tf32(av.x); dst[1] = f2tf32(av.y);
            dst[2] = f2tf32(av.z); dst[3] = f2tf32(av.w);
        }
        // --- load B tile [BK x NC] ---
#pragma unroll
        for (int it = 0; it < (BK * NC / 4) / 256; it++) {
            int idx = tid + it * 256;
            int row = idx / (NC / 4);
            int c4  = (idx % (NC / 4)) * 4;
            float4 bv = *(const float4*)&W[(kc + row) * NC + c4];
            unsigned* dst = &Bs[row * PB + c4];
            dst[0] = f2tf32(bv.x); dst[1] = f2tf32(bv.y);
            dst[2] = f2tf32(bv.z); dst[3] = f2tf32(bv.w);
        }
        __syncthreads();

#pragma unroll
        for (int kk = 0; kk < BK; kk += 8) {
            unsigned a[2][4];
#pragma unroll
            for (int mf = 0; mf < 2; mf++) {
                int r0 = wm * 32 + mf * 16;
                a[mf][0] = As[(r0 + g)     * PA + kk + t];
                a[mf][1] = As[(r0 + g + 8) * PA + kk + t];
                a[mf][2] = As[(r0 + g)     * PA + kk + t + 4];
                a[mf][3] = As[(r0 + g + 8) * PA + kk + t + 4];
            }
            unsigned b[NF][2];
#pragma unroll
            for (int nf = 0; nf < NF; nf++) {
                int c0 = wn * NF * 8 + nf * 8 + g;
                b[nf][0] = Bs[(kk + t)     * PB + c0];
                b[nf][1] = Bs[(kk + t + 4) * PB + c0];
            }
#pragma unroll
            for (int mf = 0; mf < 2; mf++)
#pragma unroll
                for (int nf = 0; nf < NF; nf++) {
                    asm volatile(
                        "mma.sync.aligned.m16n8k8.row.col.f32.tf32.tf32.f32 "
                        "{%0,%1,%2,%3}, {%4,%5,%6,%7}, {%8,%9}, {%0,%1,%2,%3};\n"
                        : "+f"(acc[mf][nf][0]), "+f"(acc[mf][nf][1]),
                          "+f"(acc[mf][nf][2]), "+f"(acc[mf][nf][3])
                        : "r"(a[mf][0]), "r"(a[mf][1]), "r"(a[mf][2]), "r"(a[mf][3]),
                          "r"(b[nf][0]), "r"(b[nf][1]));
                }
        }
        __syncthreads();
    }

    // epilogue: dinv row scale + store
#pragma unroll
    for (int mf = 0; mf < 2; mf++) {
        int r0 = rowBase + wm * 32 + mf * 16 + g;
        int r1 = r0 + 8;
        float d0 = (r0 < M) ? g_dinv[r0] : 0.f;
        float d1 = (r1 < M) ? g_dinv[r1] : 0.f;
#pragma unroll
        for (int nf = 0; nf < NF; nf++) {
            int col = wn * NF * 8 + nf * 8 + 2 * t;
            if (r0 < M) {
                float2 v0 = make_float2(d0 * acc[mf][nf][0], d0 * acc[mf][nf][1]);
                *(float2*)&C[(long long)r0 * NC + col] = v0;
            }
            if (r1 < M) {
                float2 v1 = make_float2(d1 * acc[mf][nf][2], d1 * acc[mf][nf][3]);
                *(float2*)&C[(long long)r1 * NC + col] = v1;
            }
        }
    }
}

// ---------------------------------------------------------------------------
// Pull aggregation layer 1: warp per node, 128 channels as float4 per lane.
__global__ __launch_bounds__(256) void k_pull1(const float* __restrict__ b1, int n) {
    int w = (blockIdx.x * blockDim.x + threadIdx.x) >> 5;
    int lane = threadIdx.x & 31;
    if (w >= n) return;
    const float4* t1v = (const float4*)g_t1;
    float4 acc = t1v[(long long)w * 32 + lane];
    int e0 = g_off[w], e1 = g_off[w + 1];
    for (int e = e0; e < e1; e++) {
        int s = g_srcl[e];
        float4 v = t1v[(long long)s * 32 + lane];
        acc.x += v.x; acc.y += v.y; acc.z += v.z; acc.w += v.w;
    }
    float di = g_dinv[w];
    float4 bb = ((const float4*)b1)[lane];
    float4 r;
    r.x = fmaxf(fmaf(di, acc.x, bb.x), 0.0f);
    r.y = fmaxf(fmaf(di, acc.y, bb.y), 0.0f);
    r.z = fmaxf(fmaf(di, acc.z, bb.z), 0.0f);
    r.w = fmaxf(fmaf(di, acc.w, bb.w), 0.0f);
    ((float4*)g_r)[(long long)w * 32 + lane] = r;
}

// Pull aggregation layer 2: warp per node, 64 channels as float2 per lane.
__global__ __launch_bounds__(256) void k_pull2(const float* __restrict__ b2,
                                               float* __restrict__ out, int n) {
    int w = (blockIdx.x * blockDim.x + threadIdx.x) >> 5;
    int lane = threadIdx.x & 31;
    if (w >= n) return;
    const float2* t2v = (const float2*)g_t2;
    float2 acc = t2v[(long long)w * 32 + lane];
    int e0 = g_off[w], e1 = g_off[w + 1];
    for (int e = e0; e < e1; e++) {
        int s = g_srcl[e];
        float2 v = t2v[(long long)s * 32 + lane];
        acc.x += v.x; acc.y += v.y;
    }
    float di = g_dinv[w];
    float2 bb = ((const float2*)b2)[lane];
    float2 r;
    r.x = fmaf(di, acc.x, bb.x);
    r.y = fmaf(di, acc.y, bb.y);
    ((float2*)out)[(long long)w * 32 + lane] = r;
}

// ---------------------------------------------------------------------------
extern "C" void kernel_launch(void* const* d_in, const int* in_sizes, int n_in,
                              void* d_out, int out_size) {
    const float* x  = (const float*)d_in[0];
    const void*  ei = d_in[1];
    const float* W1 = (const float*)d_in[2];
    const float* b1 = (const float*)d_in[3];
    const float* W2 = (const float*)d_in[4];
    const float* b2 = (const float*)d_in[5];
    float* out = (float*)d_out;

    int N = in_sizes[0] / C1;            // 50000
    long long E = in_sizes[1] / 2;       // 800000

    float *p_t1 = nullptr, *p_r = nullptr, *p_t2 = nullptr;
    cudaGetSymbolAddress((void**)&p_t1, g_t1);
    cudaGetSymbolAddress((void**)&p_r,  g_r);
    cudaGetSymbolAddress((void**)&p_t2, g_t2);

    k_detect<<<1, 32>>>(ei, N, E);

    int gN = (N + 255) / 256;
    long long gE = (E + 255) / 256;

    k_zero_cnt<<<gN, 256>>>(N);
    k_count<<<(unsigned)gE, 256>>>(ei, E);

    int nb = (N + 1023) / 1024;
    k_scan1<<<nb, 1024>>>(N);
    k_scan2<<<1, 64>>>(nb);
    k_scan3<<<gN, 256>>>(N, E);
    k_bucket<<<(unsigned)gE, 256>>>(ei, E);

    int gg = (N + 127) / 128;
    k_gemm_tf32<C1><<<gg, 256>>>(x, W1, p_t1, N);

    long long warpThreads = (long long)N * 32;
    int gw = (int)((warpThreads + 255) / 256);
    k_pull1<<<gw, 256>>>(b1, N);

    k_gemm_tf32<C2><<<gg, 256>>>(p_r, W2, p_t2, N);

    k_pull2<<<gw, 256>>>(b2, out, N);
}

// round 5
// speedup vs baseline: 1.7085x; 1.0797x over previous
#include <cuda_runtime.h>
#include <cuda_bf16.h>
#include <cuda_fp16.h>

// GCN 2-layer forward, pull-based aggregation via per-launch CSR build.
//   t1h = fp16( dinv[i] * (x @ W1) )             [tf32 tensor-core GEMM]
//   r   = relu(dinv[i] * (t1h[i] + sum t1h[src]) + b1)   [fp32 accum]
//   t2  = dinv[i] * (r @ W2)                     [tf32 tensor-core GEMM]
//   out = dinv[i] * (t2[i] + sum t2[src]) + b2

#define MAXN 50000
#define MAXE 800000
#define C1 128
#define C2 64

__device__ int    g_is64;
__device__ int    g_cnt[MAXN];
__device__ int    g_off[MAXN + 1];
__device__ int    g_cur[MAXN];
__device__ int    g_srcl[MAXE];
__device__ int    g_part[64];
__device__ float  g_dinv[MAXN];
__device__ __half g_t1h[MAXN * C1];
__device__ float  g_r[MAXN * C1];
__device__ float  g_t2[MAXN * C2];

// ---------------------------------------------------------------------------
__global__ void k_detect(const void* ei, int n_nodes, long long safe_words) {
    if (threadIdx.x == 0 && blockIdx.x == 0) {
        const unsigned long long* p = (const unsigned long long*)ei;
        long long cnt = safe_words < 64 ? safe_words : 64;
        int ok64 = 1;
        for (long long i = 0; i < cnt; i++) {
            if (p[i] >= (unsigned long long)n_nodes) { ok64 = 0; break; }
        }
        g_is64 = ok64;
    }
}

__device__ __forceinline__ int load_edge(const void* ei, long long idx, int is64) {
    if (is64) return (int)((const long long*)ei)[idx];
    return ((const int*)ei)[idx];
}

__global__ void k_zero_cnt(int n) {
    int i = blockIdx.x * blockDim.x + threadIdx.x;
    if (i < n) g_cnt[i] = 0;
}

__global__ void k_count(const void* ei, long long E) {
    long long e = (long long)blockIdx.x * blockDim.x + threadIdx.x;
    if (e < E) {
        int d = load_edge(ei, E + e, g_is64);
        atomicAdd(&g_cnt[d], 1);
    }
}

__global__ void k_scan1(int n) {
    __shared__ int s[1024];
    int tid = threadIdx.x;
    int gid = blockIdx.x * 1024 + tid;
    int v = (gid < n) ? g_cnt[gid] : 0;
    s[tid] = v;
    __syncthreads();
#pragma unroll
    for (int o = 1; o < 1024; o <<= 1) {
        int t = (tid >= o) ? s[tid - o] : 0;
        __syncthreads();
        s[tid] += t;
        __syncthreads();
    }
    if (gid < n) g_off[gid] = s[tid] - v;
    if (tid == 1023) g_part[blockIdx.x] = s[tid];
}

__global__ void k_scan2(int nb) {
    __shared__ int s[64];
    int tid = threadIdx.x;
    int v = (tid < nb) ? g_part[tid] : 0;
    s[tid] = v;
    __syncthreads();
#pragma unroll
    for (int o = 1; o < 64; o <<= 1) {
        int t = (tid >= o) ? s[tid - o] : 0;
        __syncthreads();
        s[tid] += t;
        __syncthreads();
    }
    if (tid < nb) g_part[tid] = s[tid] - v;
}

__global__ void k_scan3(int n, long long E) {
    int i = blockIdx.x * blockDim.x + threadIdx.x;
    if (i < n) {
        int off = g_off[i] + g_part[i >> 10];
        g_off[i] = off;
        g_cur[i] = off;
        g_dinv[i] = rsqrtf((float)(g_cnt[i] + 1));
    }
    if (i == 0) g_off[n] = (int)E;
}

__global__ void k_bucket(const void* ei, long long E) {
    long long e = (long long)blockIdx.x * blockDim.x + threadIdx.x;
    if (e < E) {
        int is64 = g_is64;
        int s = load_edge(ei, e, is64);
        int d = load_edge(ei, E + e, is64);
        int pos = atomicAdd(&g_cur[d], 1);
        g_srcl[pos] = s;
    }
}

// ---------------------------------------------------------------------------
// tf32 tensor-core GEMM: C[m][c] = dinv[m] * sum_k A[m][k] * W[k][c]
// K=128 fixed. BM=128, BK=32, 256 threads (8 warps).
// HALF_OUT: store __half (for t1h), else float.
__device__ __forceinline__ unsigned f2tf32(float f) {
    unsigned u;
    asm("cvt.rna.tf32.f32 %0, %1;" : "=r"(u) : "f"(f));
    return u;
}

template <int NC, bool HALF_OUT>
__global__ __launch_bounds__(256) void k_gemm_tf32(
    const float* __restrict__ A, const float* __restrict__ W,
    void* __restrict__ Cout, int M)
{
    constexpr int K   = 128;
    constexpr int BM  = 128;
    constexpr int BK  = 32;
    constexpr int PA  = BK + 4;
    constexpr int PB  = NC + 4;
    constexpr int NF  = NC / 16;

    __shared__ unsigned As[BM * PA];
    __shared__ unsigned Bs[BK * PB];

    int tid  = threadIdx.x;
    int wid  = tid >> 5;
    int lane = tid & 31;
    int wm   = wid >> 1;
    int wn   = wid & 1;
    int g    = lane >> 2;
    int t    = lane & 3;
    int rowBase = blockIdx.x * BM;

    float acc[2][NF][4];
#pragma unroll
    for (int mf = 0; mf < 2; mf++)
#pragma unroll
        for (int nf = 0; nf < NF; nf++)
#pragma unroll
            for (int i = 0; i < 4; i++) acc[mf][nf][i] = 0.0f;

    for (int kc = 0; kc < K; kc += BK) {
#pragma unroll
        for (int it = 0; it < (BM * BK / 4) / 256; it++) {
            int idx = tid + it * 256;
            int row = idx >> 3;
            int c4  = (idx & 7) * 4;
            int gr  = rowBase + row;
            float4 av = make_float4(0.f, 0.f, 0.f, 0.f);
            if (gr < M) av = *(const float4*)&A[(long long)gr * K + kc + c4];
            unsigned* dst = &As[row * PA + c4];
            dst[0] = f2tf32(av.x); dst[1] = f2tf32(av.y);
            dst[2] = f2tf32(av.z); dst[3] = f2tf32(av.w);
        }
#pragma unroll
        for (int it = 0; it < (BK * NC / 4) / 256; it++) {
            int idx = tid + it * 256;
            int row = idx / (NC / 4);
            int c4  = (idx % (NC / 4)) * 4;
            float4 bv = *(const float4*)&W[(kc + row) * NC + c4];
            unsigned* dst = &Bs[row * PB + c4];
            dst[0] = f2tf32(bv.x); dst[1] = f2tf32(bv.y);
            dst[2] = f2tf32(bv.z); dst[3] = f2tf32(bv.w);
        }
        __syncthreads();

#pragma unroll
        for (int kk = 0; kk < BK; kk += 8) {
            unsigned a[2][4];
#pragma unroll
            for (int mf = 0; mf < 2; mf++) {
                int r0 = wm * 32 + mf * 16;
                a[mf][0] = As[(r0 + g)     * PA + kk + t];
                a[mf][1] = As[(r0 + g + 8) * PA + kk + t];
                a[mf][2] = As[(r0 + g)     * PA + kk + t + 4];
                a[mf][3] = As[(r0 + g + 8) * PA + kk + t + 4];
            }
            unsigned b[NF][2];
#pragma unroll
            for (int nf = 0; nf < NF; nf++) {
                int c0 = wn * NF * 8 + nf * 8 + g;
                b[nf][0] = Bs[(kk + t)     * PB + c0];
                b[nf][1] = Bs[(kk + t + 4) * PB + c0];
            }
#pragma unroll
            for (int mf = 0; mf < 2; mf++)
#pragma unroll
                for (int nf = 0; nf < NF; nf++) {
                    asm volatile(
                        "mma.sync.aligned.m16n8k8.row.col.f32.tf32.tf32.f32 "
                        "{%0,%1,%2,%3}, {%4,%5,%6,%7}, {%8,%9}, {%0,%1,%2,%3};\n"
                        : "+f"(acc[mf][nf][0]), "+f"(acc[mf][nf][1]),
                          "+f"(acc[mf][nf][2]), "+f"(acc[mf][nf][3])
                        : "r"(a[mf][0]), "r"(a[mf][1]), "r"(a[mf][2]), "r"(a[mf][3]),
                          "r"(b[nf][0]), "r"(b[nf][1]));
                }
        }
        __syncthreads();
    }

    // epilogue: dinv row scale + store (fp32 or fp16)
#pragma unroll
    for (int mf = 0; mf < 2; mf++) {
        int r0 = rowBase + wm * 32 + mf * 16 + g;
        int r1 = r0 + 8;
        float d0 = (r0 < M) ? g_dinv[r0] : 0.f;
        float d1 = (r1 < M) ? g_dinv[r1] : 0.f;
#pragma unroll
        for (int nf = 0; nf < NF; nf++) {
            int col = wn * NF * 8 + nf * 8 + 2 * t;
            if (HALF_OUT) {
                __half* C = (__half*)Cout;
                if (r0 < M) {
                    __half2 h0 = __floats2half2_rn(d0 * acc[mf][nf][0], d0 * acc[mf][nf][1]);
                    *(__half2*)&C[(long long)r0 * NC + col] = h0;
                }
                if (r1 < M) {
                    __half2 h1 = __floats2half2_rn(d1 * acc[mf][nf][2], d1 * acc[mf][nf][3]);
                    *(__half2*)&C[(long long)r1 * NC + col] = h1;
                }
            } else {
                float* C = (float*)Cout;
                if (r0 < M) {
                    float2 v0 = make_float2(d0 * acc[mf][nf][0], d0 * acc[mf][nf][1]);
                    *(float2*)&C[(long long)r0 * NC + col] = v0;
                }
                if (r1 < M) {
                    float2 v1 = make_float2(d1 * acc[mf][nf][2], d1 * acc[mf][nf][3]);
                    *(float2*)&C[(long long)r1 * NC + col] = v1;
                }
            }
        }
    }
}

// ---------------------------------------------------------------------------
// Pull layer 1: warp per node, 128 fp16 channels, 4 per lane (uint2), fp32 accum.
__global__ __launch_bounds__(256) void k_pull1(const float* __restrict__ b1, int n) {
    int w = (blockIdx.x * blockDim.x + threadIdx.x) >> 5;
    int lane = threadIdx.x & 31;
    if (w >= n) return;
    const uint2* t1v = (const uint2*)g_t1h;   // 8B = 4 halves per lane

    uint2 selfv = t1v[(long long)w * 32 + lane];
    __half2 s0 = *(__half2*)&selfv.x;
    __half2 s1 = *(__half2*)&selfv.y;
    float2 f0 = __half22float2(s0);
    float2 f1 = __half22float2(s1);
    float4 acc = make_float4(f0.x, f0.y, f1.x, f1.y);

    int e0 = g_off[w], e1 = g_off[w + 1];
    for (int e = e0; e < e1; e++) {
        int s = g_srcl[e];
        uint2 v = t1v[(long long)s * 32 + lane];
        float2 a = __half22float2(*(__half2*)&v.x);
        float2 b = __half22float2(*(__half2*)&v.y);
        acc.x += a.x; acc.y += a.y; acc.z += b.x; acc.w += b.y;
    }
    float di = g_dinv[w];
    float4 bb = ((const float4*)b1)[lane];
    float4 r;
    r.x = fmaxf(fmaf(di, acc.x, bb.x), 0.0f);
    r.y = fmaxf(fmaf(di, acc.y, bb.y), 0.0f);
    r.z = fmaxf(fmaf(di, acc.z, bb.z), 0.0f);
    r.w = fmaxf(fmaf(di, acc.w, bb.w), 0.0f);
    ((float4*)g_r)[(long long)w * 32 + lane] = r;
}

// Pull layer 2: warp per node, 64 fp32 channels, 2 per lane.
__global__ __launch_bounds__(256) void k_pull2(const float* __restrict__ b2,
                                               float* __restrict__ out, int n) {
    int w = (blockIdx.x * blockDim.x + threadIdx.x) >> 5;
    int lane = threadIdx.x & 31;
    if (w >= n) return;
    const float2* t2v = (const float2*)g_t2;
    float2 acc = t2v[(long long)w * 32 + lane];
    int e0 = g_off[w], e1 = g_off[w + 1];
    for (int e = e0; e < e1; e++) {
        int s = g_srcl[e];
        float2 v = t2v[(long long)s * 32 + lane];
        acc.x += v.x; acc.y += v.y;
    }
    float di = g_dinv[w];
    float2 bb = ((const float2*)b2)[lane];
    float2 r;
    r.x = fmaf(di, acc.x, bb.x);
    r.y = fmaf(di, acc.y, bb.y);
    ((float2*)out)[(long long)w * 32 + lane] = r;
}

// ---------------------------------------------------------------------------
extern "C" void kernel_launch(void* const* d_in, const int* in_sizes, int n_in,
                              void* d_out, int out_size) {
    const float* x  = (const float*)d_in[0];
    const void*  ei = d_in[1];
    const float* W1 = (const float*)d_in[2];
    const float* b1 = (const float*)d_in[3];
    const float* W2 = (const float*)d_in[4];
    const float* b2 = (const float*)d_in[5];
    float* out = (float*)d_out;

    int N = in_sizes[0] / C1;            // 50000
    long long E = in_sizes[1] / 2;       // 800000

    void *p_t1h = nullptr, *p_r = nullptr, *p_t2 = nullptr;
    cudaGetSymbolAddress(&p_t1h, g_t1h);
    cudaGetSymbolAddress(&p_r,   g_r);
    cudaGetSymbolAddress(&p_t2,  g_t2);

    k_detect<<<1, 32>>>(ei, N, E);

    int gN = (N + 255) / 256;
    long long gE = (E + 255) / 256;

    k_zero_cnt<<<gN, 256>>>(N);
    k_count<<<(unsigned)gE, 256>>>(ei, E);

    int nb = (N + 1023) / 1024;
    k_scan1<<<nb, 1024>>>(N);
    k_scan2<<<1, 64>>>(nb);
    k_scan3<<<gN, 256>>>(N, E);
    k_bucket<<<(unsigned)gE, 256>>>(ei, E);

    int gg = (N + 127) / 128;
    k_gemm_tf32<C1, true><<<gg, 256>>>(x, W1, p_t1h, N);

    long long warpThreads = (long long)N * 32;
    int gw = (int)((warpThreads + 255) / 256);
    k_pull1<<<gw, 256>>>(b1, N);

    k_gemm_tf32<C2, false><<<gg, 256>>>((const float*)p_r, W2, p_t2, N);

    k_pull2<<<gw, 256>>>(b2, out, N);
}